// round 5
// baseline (speedup 1.0000x reference)
#include <cuda_runtime.h>
#include <math.h>
#include <stdint.h>

#define BB  32
#define MM  65536
#define WD  32
#define RR  4
#define KK  16
#define CC  65
#define INS 256
#define NEG_INF (-3.402823e38f)
#define POS_INF ( 3.402823e38f)
#define FULLMASK 0xffffffffu

// ---------------- scratch ----------------
__device__ __align__(16) float g_rq[BB * RR * WD];
__device__ __align__(16) float g_newvis[BB * CC * WD];
__device__ float g_newusage[BB * CC];
__device__ int   g_topk[BB * RR * KK];
// candidates: per (b,r): 32 chunks * 16 = 512
__device__ __align__(16) unsigned g_cand_v[BB * RR * 512];
__device__ __align__(16) int      g_cand_i[BB * RR * 512];
// segmented argmin partials: per b: 32 segments
__device__ float g_seg_minv[BB * 32];
__device__ int   g_seg_mini[BB * 32];

// order-preserving float <-> u32 maps
__device__ __forceinline__ unsigned fmap(float x) {
    unsigned u = __float_as_uint(x);
    return (u & 0x80000000u) ? ~u : (u | 0x80000000u);
}
__device__ __forceinline__ float funmap(unsigned u) {
    unsigned v = (u & 0x80000000u) ? (u & 0x7fffffffu) : ~u;
    return __uint_as_float(v);
}

__device__ __forceinline__ unsigned smem_u32(const void* p) {
    return (unsigned)__cvta_generic_to_shared(p);
}
__device__ __forceinline__ void mbar_init(unsigned mbar) {
    asm volatile("mbarrier.init.shared.b64 [%0], %1;" :: "r"(mbar), "r"(1u) : "memory");
}
__device__ __forceinline__ void mbar_expect_tx(unsigned mbar, unsigned bytes) {
    asm volatile("mbarrier.arrive.expect_tx.shared.b64 _, [%0], %1;"
                 :: "r"(mbar), "r"(bytes) : "memory");
}
__device__ __forceinline__ void mbar_wait(unsigned mbar, unsigned parity) {
    asm volatile(
        "{\n\t"
        ".reg .pred P;\n\t"
        "WAIT_%=:\n\t"
        "mbarrier.try_wait.parity.acquire.cta.shared::cta.b64 P, [%0], %1;\n\t"
        "@!P bra WAIT_%=;\n\t"
        "}"
        :: "r"(mbar), "r"(parity) : "memory");
}
__device__ __forceinline__ void bulk_g2s(unsigned dst, const void* src, unsigned bytes, unsigned mbar) {
    asm volatile("cp.async.bulk.shared::cta.global.mbarrier::complete_tx::bytes [%0], [%1], %2, [%3];"
                 :: "r"(dst), "l"(src), "r"(bytes), "r"(mbar) : "memory");
}
__device__ __forceinline__ void fence_proxy_async_cta() {
    asm volatile("fence.proxy.async.shared::cta;" ::: "memory");
}

// ---------------- kernel 1: projections + write-phase ----------------
__global__ void k_setup(const float* __restrict__ xi,
                        const float* __restrict__ rw,
                        const float* __restrict__ ww,
                        const float* __restrict__ usage,
                        const float* __restrict__ vis,
                        const float* __restrict__ Wrq, const float* __restrict__ brq,
                        const float* __restrict__ Wwv, const float* __restrict__ bwv,
                        const float* __restrict__ Wig, const float* __restrict__ big,
                        const float* __restrict__ Wwg, const float* __restrict__ bwg,
                        const int* __restrict__ rpos,
                        const int* __restrict__ tptr)
{
    int b = blockIdx.x;
    int t = threadIdx.x;          // 256
    int w = t >> 5, l = t & 31;
    int sub = l & 7;

    __shared__ float4 s_xi4[INS / 4];
    __shared__ float s_wv[WD];
    __shared__ float s_ig[CC];
    __shared__ float s_wg;
    __shared__ float s_ru[CC], s_rwg[CC], s_wwg[CC], s_I[CC], s_wwn[CC];
    __shared__ float s_minu;
    __shared__ int   s_p[CC];

    if (t < 64) s_xi4[t] = ((const float4*)(xi + b * INS))[t];
    __syncthreads();

#pragma unroll 1
    for (int pass = 0; pass < 8; pass++) {
        int row = pass * 32 + w * 4 + (l >> 3);
        float acc = 0.f;
        if (row < 226) {
            const float4* wp;
            if (row < 128)      wp = (const float4*)(Wrq + row * INS);
            else if (row < 160) wp = (const float4*)(Wwv + (row - 128) * INS);
            else if (row < 225) wp = (const float4*)(Wig + (row - 160) * INS);
            else                wp = (const float4*)Wwg;
#pragma unroll
            for (int m = 0; m < 8; m++) {
                float4 a = wp[sub + m * 8];
                float4 q = s_xi4[sub + m * 8];
                acc += a.x * q.x + a.y * q.y + a.z * q.z + a.w * q.w;
            }
        }
        acc += __shfl_xor_sync(0xffffffffu, acc, 1);
        acc += __shfl_xor_sync(0xffffffffu, acc, 2);
        acc += __shfl_xor_sync(0xffffffffu, acc, 4);
        if (sub == 0 && row < 226) {
            if (row < 128)      g_rq[b * 128 + row] = acc + brq[row];
            else if (row < 160) s_wv[row - 128] = acc + bwv[row - 128];
            else if (row < 225) s_ig[row - 160] = 1.0f / (1.0f + expf(-(acc + big[row - 160])));
            else                s_wg = 1.0f / (1.0f + expf(-(acc + bwg[0])));
        }
    }

    int ts = tptr ? *tptr : 2;

    if (t < CC) {
        int p = rpos[b * CC + t];
        s_p[t] = p;
        float rg = rw[(size_t)b * MM + p];
        if (ts == 1) rg += 1.0f;
        s_rwg[t] = rg;
        s_wwg[t] = ww[(size_t)b * MM + p];
        s_ru[t]  = usage[(size_t)b * MM + p];
    }
    __syncthreads();
    if (t == 0) {
        float mn = s_ru[0];
        for (int c = 1; c < CC; c++) mn = fminf(mn, s_ru[c]);
        s_minu = mn;
    }
    __syncthreads();
    if (t < CC) {
        float I = (s_ru[t] == s_minu) ? 1.0f : 0.0f;
        s_I[t] = I;
        float u = ((s_rwg[t] + s_wwg[t]) > 0.005f) ? 1.0f : 0.0f;
        float nru = (u > 0.0f) ? ((float)ts - s_ru[t]) : s_ru[t];
        g_newusage[b * CC + t] = nru;
        s_wwn[t] = s_wg * (s_ig[t] * s_rwg[t] + (1.0f - s_ig[t]) * I);
    }
    __syncthreads();
    for (int idx = t; idx < CC * WD; idx += blockDim.x) {
        int c = idx >> 5, ww2 = idx & 31;
        float nv = vis[(size_t)b * CC * WD + idx] * (1.0f - s_I[c]) + s_wwn[c] * s_wv[ww2];
        g_newvis[(size_t)b * CC * WD + idx] = nv;
    }
}

// ---------------- block-level top-16 selection over 2048-row chunk ----------------
__device__ __forceinline__ void select16(unsigned (&u)[16], int t, int w, int l,
                                         int chunkbase,
                                         unsigned* s_wm, unsigned* s_wk, unsigned* s_bk,
                                         unsigned* outv, int* outi)
{
    unsigned lm = u[0];
    unsigned lkey = (unsigned)t;
#pragma unroll
    for (int s = 1; s < 16; s++)
        if (u[s] > lm) { lm = u[s]; lkey = (unsigned)(s * 128 + t); }

    for (int round = 0; round < 16; round++) {
        int par = round & 1;
        unsigned m_w = __reduce_max_sync(FULLMASK, lm);
        unsigned key = (lm == m_w) ? lkey : 0xffffffffu;
        unsigned k_w = __reduce_min_sync(FULLMASK, key);
        if (l == 0) { s_wm[par * 4 + w] = m_w; s_wk[par * 4 + w] = k_w; }
        __syncthreads();
        if (t == 0) {
            unsigned bm = s_wm[par * 4], bk = s_wk[par * 4];
#pragma unroll
            for (int w2 = 1; w2 < 4; w2++) {
                unsigned vm2 = s_wm[par * 4 + w2], vk2 = s_wk[par * 4 + w2];
                if (vm2 > bm || (vm2 == bm && vk2 < bk)) { bm = vm2; bk = vk2; }
            }
            s_bk[par] = bk;
            outv[round] = bm;
            outi[round] = chunkbase + (int)bk;
        }
        __syncthreads();
        unsigned bk = s_bk[par];
        if ((bk & 127u) == (unsigned)t) {
            int slot = (int)(bk >> 7);
#pragma unroll
            for (int s = 0; s < 16; s++) if (s == slot) u[s] = 0u;
            lm = u[0]; lkey = (unsigned)t;
#pragma unroll
            for (int s = 1; s < 16; s++)
                if (u[s] > lm) { lm = u[s]; lkey = (unsigned)(s * 128 + t); }
        }
    }
}

// ---------------- kernel 2: TMA-bulk pipelined scores + top-16 + usage argmin ----------------
__global__ void __launch_bounds__(128, 4) k_scores(const float* __restrict__ memory,
                                                   const float* __restrict__ usage,
                                                   const int* __restrict__ rpos)
{
    int b = blockIdx.y;
    int chunk = blockIdx.x;      // 32 chunks of 2048 rows
    int t = threadIdx.x;         // 128
    int w = t >> 5, l = t & 31;
    int chunkbase = chunk * 2048;

    __shared__ __align__(16) float4 s_t[2][128 * 8];   // two 16 KB tiles, linear layout
    __shared__ float4 s_q4[RR * 8];
    __shared__ int   s_p[CC];
    __shared__ int   s_last[CC];
    __shared__ unsigned s_wm[8], s_wk[8], s_bk[2];
    __shared__ unsigned s_bm[64];
    __shared__ __align__(8) unsigned long long s_mbar[2];

    if (t < 64)     s_bm[t] = 0u;
    if (t < RR * 8) s_q4[t] = ((const float4*)g_rq)[b * RR * 8 + t];
    if (t < CC)     s_p[t] = rpos[b * CC + t];
    if (t == 0) {
        mbar_init(smem_u32(&s_mbar[0]));
        mbar_init(smem_u32(&s_mbar[1]));
    }
    __syncthreads();
    if (t < CC) {
        int lastf = 1;
        for (int c2 = t + 1; c2 < CC; c2++) if (s_p[c2] == s_p[t]) { lastf = 0; break; }
        s_last[t] = lastf;
        int p = s_p[t];
        if (p >= chunkbase && p < chunkbase + 2048) {
            int loc = p - chunkbase;
            atomicOr(&s_bm[loc >> 5], 1u << (loc & 31));
        }
    }

    const float* gbase = memory + ((size_t)b * MM + chunkbase) * WD;
    unsigned mb0 = smem_u32(&s_mbar[0]), mb1 = smem_u32(&s_mbar[1]);
    unsigned st0 = smem_u32(&s_t[0][0]), st1 = smem_u32(&s_t[1][0]);

    if (t == 0) {
        mbar_expect_tx(mb0, 16384u);
        bulk_g2s(st0, gbase, 16384u, mb0);
        mbar_expect_tx(mb1, 16384u);
        bulk_g2s(st1, gbase + (size_t)128 * WD, 16384u, mb1);
    }
    __syncthreads();   // s_last / s_bm visible block-wide

    unsigned u0[16], u1[16], u2[16], u3[16];

#pragma unroll
    for (int tile = 0; tile < 16; tile++) {
        int buf = tile & 1;
        unsigned mb = buf ? mb1 : mb0;
        mbar_wait(mb, (unsigned)((tile >> 1) & 1));
        int base = chunkbase + tile * 128;
        // override updated rows (last occurrence wins)
        if (t < CC && s_last[t]) {
            int p = s_p[t];
            if (p >= base && p < base + 128) {
                int loc = p - base;
                const float4* nv = (const float4*)(g_newvis + ((size_t)b * CC + t) * WD);
#pragma unroll
                for (int j = 0; j < 8; j++) s_t[buf][loc * 8 + j] = nv[j];
            }
        }
        __syncthreads();
        float a0 = 0.f, a1 = 0.f, a2 = 0.f, a3 = 0.f;
#pragma unroll
        for (int j = 0; j < 8; j++) {
            int c = (j + t) & 7;       // rotated order: conflict-free LDS on linear tile
            float4 x = s_t[buf][t * 8 + c];
            float4 q0 = s_q4[c], q1 = s_q4[8 + c], q2 = s_q4[16 + c], q3 = s_q4[24 + c];
            a0 += x.x * q0.x + x.y * q0.y + x.z * q0.z + x.w * q0.w;
            a1 += x.x * q1.x + x.y * q1.y + x.z * q1.z + x.w * q1.w;
            a2 += x.x * q2.x + x.y * q2.y + x.z * q2.z + x.w * q2.w;
            a3 += x.x * q3.x + x.y * q3.y + x.z * q3.z + x.w * q3.w;
        }
        u0[tile] = fmap(a0); u1[tile] = fmap(a1);
        u2[tile] = fmap(a2); u3[tile] = fmap(a3);
        __syncthreads();   // all done reading buf
        if (tile < 14 && t == 0) {
            fence_proxy_async_cta();   // order generic patch writes before async reuse
            mbar_expect_tx(mb, 16384u);
            bulk_g2s(buf ? st1 : st0, gbase + (size_t)(tile + 2) * 128 * WD, 16384u, mb);
        }
    }

    // block-level top-16 per r
    {
        unsigned* bv = g_cand_v + ((size_t)(b * RR) * 32 + chunk) * 16;
        int*      bi = g_cand_i + ((size_t)(b * RR) * 32 + chunk) * 16;
        select16(u0, t, w, l, chunkbase, s_wm, s_wk, s_bk, bv,           bi);
        select16(u1, t, w, l, chunkbase, s_wm, s_wk, s_bk, bv + 32 * 16, bi + 32 * 16);
        select16(u2, t, w, l, chunkbase, s_wm, s_wk, s_bk, bv + 64 * 16, bi + 64 * 16);
        select16(u3, t, w, l, chunkbase, s_wm, s_wk, s_bk, bv + 96 * 16, bi + 96 * 16);
    }

    // fused usage argmin over this chunk (excluding scattered rows via bitmap)
    {
        const float4* u4 = (const float4*)(usage + (size_t)b * MM + chunkbase);
        unsigned bu = 0xffffffffu;
        int      bi = 0x7fffffff;
#pragma unroll
        for (int i = 0; i < 4; i++) {
            float4 x = u4[i * 128 + t];
            int lbase = (i * 128 + t) << 2;
            float xs[4] = {x.x, x.y, x.z, x.w};
#pragma unroll
            for (int j = 0; j < 4; j++) {
                int loc = lbase + j;
                unsigned uv = ((s_bm[loc >> 5] >> (loc & 31)) & 1u) ? 0xffffffffu : fmap(xs[j]);
                int gi = chunkbase + loc;
                if (uv < bu || (uv == bu && gi < bi)) { bu = uv; bi = gi; }
            }
        }
        unsigned m_w = __reduce_min_sync(FULLMASK, bu);
        unsigned key = (bu == m_w) ? (unsigned)bi : 0xffffffffu;
        unsigned k_w = __reduce_min_sync(FULLMASK, key);
        if (l == 0) { s_wm[w] = m_w; s_wk[w] = k_w; }
        __syncthreads();
        if (t == 0) {
            unsigned bm = s_wm[0], bk = s_wk[0];
#pragma unroll
            for (int w2 = 1; w2 < 4; w2++) {
                if (s_wm[w2] < bm || (s_wm[w2] == bm && s_wk[w2] < bk)) { bm = s_wm[w2]; bk = s_wk[w2]; }
            }
            g_seg_minv[b * 32 + chunk] = funmap(bm);
            g_seg_mini[b * 32 + chunk] = (int)bk;
        }
    }
}

// ---------------- kernel 3: merge 512 candidates -> top-16 per (b,r); 1 warp each ----------------
__global__ void k_topk_merge()
{
    int b = blockIdx.x;        // 32
    int t = threadIdx.x;       // 128
    int w = t >> 5, l = t & 31;
    int br = b * RR + w;

    const unsigned* cv = g_cand_v + (size_t)br * 512;
    const int*      ci = g_cand_i + (size_t)br * 512;
    unsigned v[16];
    int      id[16];
#pragma unroll
    for (int k = 0; k < 16; k++) { v[k] = cv[k * 32 + l]; id[k] = ci[k * 32 + l]; }

    unsigned lm = v[0];
    int lid_ = id[0], lslot = 0;
#pragma unroll
    for (int s = 1; s < 16; s++)
        if (v[s] > lm || (v[s] == lm && id[s] < lid_)) { lm = v[s]; lid_ = id[s]; lslot = s; }

    for (int round = 0; round < 16; round++) {
        unsigned m = __reduce_max_sync(FULLMASK, lm);
        unsigned key = (lm == m) ? (unsigned)lid_ : 0xffffffffu;
        unsigned km = __reduce_min_sync(FULLMASK, key);
        if (l == 0) g_topk[br * KK + round] = (int)km;
        if (lm == m && (unsigned)lid_ == km) {
            v[lslot] = 0u; id[lslot] = 0x7fffffff;
            lm = v[0]; lid_ = id[0]; lslot = 0;
#pragma unroll
            for (int s = 1; s < 16; s++)
                if (v[s] > lm || (v[s] == lm && id[s] < lid_)) { lm = v[s]; lid_ = id[s]; lslot = s; }
        }
    }
}

// ---------------- kernel 4: argmin combine + gather + cosine softmax ----------------
__global__ void k_final(const float* __restrict__ memory,
                        const int* __restrict__ rpos,
                        float* __restrict__ out)
{
    int b = blockIdx.x;
    int t = threadIdx.x;   // 128

    __shared__ int   s_pos[CC];
    __shared__ int   s_rp[CC];
    __shared__ float s_vm[CC * 33];
    __shared__ float s_norm[CC];
    __shared__ float s_q[RR * WD];
    __shared__ float s_kn[RR];
    __shared__ float s_wt[RR * CC];
    __shared__ float s_v[128];
    __shared__ int   s_i[128];

    s_q[t] = g_rq[b * RR * WD + t];
    if (t < RR * KK) s_pos[t] = g_topk[b * RR * KK + t];
    if (t < CC)      s_rp[t] = rpos[b * CC + t];
    __syncthreads();

    // combine argmin: 32 segment minima + 65 overridden usage values
    {
        float v = POS_INF;
        int   i = 0x7fffffff;
        if (t < 32) { v = g_seg_minv[b * 32 + t]; i = g_seg_mini[b * 32 + t]; }
        else if (t < 32 + CC) {
            int c = t - 32;
            int p = s_rp[c];
            bool last = true;
            for (int c2 = c + 1; c2 < CC; c2++) if (s_rp[c2] == p) { last = false; break; }
            if (last) { v = g_newusage[b * CC + c]; i = p; }
        }
        s_v[t] = v; s_i[t] = i;
        __syncthreads();
        for (int s = 64; s > 0; s >>= 1) {
            if (t < s) {
                if (s_v[t + s] < s_v[t] || (s_v[t + s] == s_v[t] && s_i[t + s] < s_i[t])) {
                    s_v[t] = s_v[t + s]; s_i[t] = s_i[t + s];
                }
            }
            __syncthreads();
        }
        if (t == 0) s_pos[CC - 1] = s_i[0];
    }
    __syncthreads();

    if (t < RR) {
        float s = 0.f;
        for (int w = 0; w < WD; w++) { float q = s_q[t * WD + w]; s += q * q; }
        s_kn[t] = sqrtf(s) + 1e-6f;
    }
    if (t < CC) {
        int m = s_pos[t];
        m = min(max(m, 0), MM - 1);
        const float* row = memory + ((size_t)b * MM + m) * WD;
        for (int c2 = CC - 1; c2 >= 0; c2--)
            if (s_rp[c2] == m) { row = g_newvis + ((size_t)b * CC + c2) * WD; break; }
        float s = 0.f;
        for (int w = 0; w < WD; w++) { float v = row[w]; s_vm[t * 33 + w] = v; s += v * v; }
        s_norm[t] = sqrtf(s) + 1e-6f;
    }
    __syncthreads();

    for (int idx = t; idx < RR * CC; idx += 128) {
        int r = idx / CC, c = idx % CC;
        float num = 0.f;
        for (int w = 0; w < WD; w++) num += s_vm[c * 33 + w] * s_q[r * WD + w];
        s_wt[idx] = num / ((float)WD * s_norm[c] * s_kn[r] + 1e-6f);
    }
    __syncthreads();

    if (t < RR) {
        float mx = NEG_INF;
        for (int c = 0; c < CC; c++) mx = fmaxf(mx, s_wt[t * CC + c]);
        float sum = 0.f;
        for (int c = 0; c < CC; c++) { float e = expf(s_wt[t * CC + c] - mx); s_wt[t * CC + c] = e; sum += e; }
        float inv = 1.0f / sum;
        for (int c = 0; c < CC; c++) s_wt[t * CC + c] *= inv;
    }
    __syncthreads();

    {
        int r = t >> 5, w = t & 31;
        float acc = 0.f;
        for (int c = 0; c < CC; c++) acc += s_wt[r * CC + c] * s_vm[c * 33 + w];
        out[b * RR * WD + t] = acc;
    }
}

// ---------------- launch ----------------
extern "C" void kernel_launch(void* const* d_in, const int* in_sizes, int n_in,
                              void* d_out, int out_size)
{
    const float* xi     = (const float*)d_in[0];
    const float* memory = (const float*)d_in[1];
    const float* rw     = (const float*)d_in[2];
    const float* ww     = (const float*)d_in[3];
    const float* usage  = (const float*)d_in[4];
    const float* vis    = (const float*)d_in[5];
    const float* Wrq    = (const float*)d_in[6];
    const float* brq    = (const float*)d_in[7];
    const float* Wwv    = (const float*)d_in[8];
    const float* bwv    = (const float*)d_in[9];
    const float* Wig    = (const float*)d_in[10];
    const float* big    = (const float*)d_in[11];
    const float* Wwg    = (const float*)d_in[12];
    const float* bwg    = (const float*)d_in[13];
    const int*   rpos   = (const int*)d_in[14];
    const int*   tptr   = (n_in > 16) ? (const int*)d_in[16] : nullptr;

    k_setup<<<BB, 256>>>(xi, rw, ww, usage, vis, Wrq, brq, Wwv, bwv,
                         Wig, big, Wwg, bwg, rpos, tptr);
    k_scores<<<dim3(32, BB), 128>>>(memory, usage, rpos);
    k_topk_merge<<<BB, 128>>>();
    k_final<<<BB, 128>>>(memory, rpos, (float*)d_out);
}